// round 8
// baseline (speedup 1.0000x reference)
#include <cuda_runtime.h>
#include <cuda_bf16.h>

// Problem constants (fixed shapes from reference)
#define B_     128
#define C_     1024
#define HW_    196          // 14*14
#define VEC_   49           // 196/4 float4 per channel row
#define CHUNKS 16           // channel chunks per sample
#define CPB    64           // channels per block (C_/CHUNKS)
#define THREADS 256         // 8 warps
#define NPART  (B_*CHUNKS)  // 2048 partials

#define MARGIN 1.0f
#define EPS    1e-6f

__device__ float g_partials[NPART];

__global__ __launch_bounds__(THREADS)
void ffl_main_kernel(const float* __restrict__ feat,
                     const float* __restrict__ feat_p,
                     const float* __restrict__ avg_feat,   // [2,1024]
                     const int* __restrict__ qual,         // [128] int32
                     const int* __restrict__ label)        // [128] int32
{
    const int chunk = blockIdx.x;        // 0..15
    const int b     = blockIdx.y;        // 0..127
    const int tid   = threadIdx.x;
    const int warp  = tid >> 5;          // 0..7
    const int lane  = tid & 31;

    // Select source tensor for this sample (only this one is read)
    const int q  = qual[b];
    const float* __restrict__ src = (q == 1) ? feat : feat_p;
    const int lb = label[b] & 1;   // mask: guaranteed in-bounds gather
    const float* __restrict__ af_pos = avg_feat + (size_t)lb * C_;
    const float* __restrict__ af_neg = avg_feat + (size_t)(1 - lb) * C_;

    float acc = 0.0f;  // per-warp accumulated loss contribution

    // Each warp handles channels chunk*64 + warp, step 8  -> 8 channels
    #pragma unroll
    for (int it = 0; it < CPB / 8; ++it) {
        const int c = chunk * CPB + warp + it * 8;
        const float4* __restrict__ row =
            reinterpret_cast<const float4*>(src + ((size_t)b * C_ + c) * HW_);

        // 49 float4 per row: lane loads [lane] and (lane<17) [lane+32]
        float4 v0 = row[lane];
        float s = v0.x + v0.y + v0.z + v0.w;
        if (lane < VEC_ - 32) {
            float4 v1 = row[lane + 32];
            s += v1.x + v1.y + v1.z + v1.w;
        }
        // warp reduce
        #pragma unroll
        for (int off = 16; off > 0; off >>= 1)
            s += __shfl_xor_sync(0xFFFFFFFFu, s, off);

        if (lane == 0) {
            const float sel  = s * (1.0f / (float)HW_);
            const float d_ap = fabsf(sel - af_pos[c] + EPS);
            const float d_an = fabsf(sel - af_neg[c] + EPS);
            acc += fmaxf(d_ap - d_an + MARGIN, 0.0f);
        }
    }

    // Block reduce the 8 warp-leader partials (deterministic fixed order)
    __shared__ float warp_acc[8];
    if (lane == 0) warp_acc[warp] = acc;
    __syncthreads();
    if (tid == 0) {
        float t = 0.0f;
        #pragma unroll
        for (int w = 0; w < 8; ++w) t += warp_acc[w];
        g_partials[b * CHUNKS + chunk] = t * (1.0f / (float)C_);
    }
}

__global__ __launch_bounds__(THREADS)
void ffl_reduce_kernel(float* __restrict__ out)
{
    const int tid = threadIdx.x;
    float s = 0.0f;
    #pragma unroll
    for (int i = 0; i < NPART / THREADS; ++i)      // 2048/256 = 8
        s += g_partials[tid + i * THREADS];

    __shared__ float sm[THREADS];
    sm[tid] = s;
    __syncthreads();
    #pragma unroll
    for (int step = THREADS / 2; step > 0; step >>= 1) {
        if (tid < step) sm[tid] += sm[tid + step];
        __syncthreads();
    }
    if (tid == 0) out[0] = sm[0];
}

extern "C" void kernel_launch(void* const* d_in, const int* in_sizes, int n_in,
                              void* d_out, int out_size)
{
    const float* feat     = (const float*)d_in[0];
    const float* feat_p   = (const float*)d_in[1];
    const float* avg_feat = (const float*)d_in[2];
    const int*   qual     = (const int*)d_in[3];
    const int*   label    = (const int*)d_in[4];
    float* out = (float*)d_out;

    dim3 grid(CHUNKS, B_);
    ffl_main_kernel<<<grid, THREADS>>>(feat, feat_p, avg_feat, qual, label);
    ffl_reduce_kernel<<<1, THREADS>>>(out);
}

// round 9
// speedup vs baseline: 1.3272x; 1.3272x over previous
#include <cuda_runtime.h>
#include <cuda_bf16.h>

// Problem constants (fixed shapes from reference)
#define B_     128
#define C_     1024
#define HW_    196          // 14*14
#define VEC_   49           // 196/4 float4 per channel row
#define CHUNKS 16           // channel chunks per sample
#define CPB    64           // channels per block (C_/CHUNKS)
#define THREADS 256         // 8 warps
#define NPART  (B_*CHUNKS)  // 2048 partials (one per block)

#define MARGIN 1.0f
#define EPS    1e-6f

__device__ float g_partials[NPART];
__device__ unsigned int g_ticket = 0;   // self-resetting; replay-safe

__global__ __launch_bounds__(THREADS)
void ffl_fused_kernel(const float* __restrict__ feat,
                      const float* __restrict__ feat_p,
                      const float* __restrict__ avg_feat,   // [2,1024]
                      const int* __restrict__ qual,         // [128] int32
                      const int* __restrict__ label,        // [128] int32
                      float* __restrict__ out)
{
    const int chunk = blockIdx.x;        // 0..15
    const int b     = blockIdx.y;        // 0..127
    const int tid   = threadIdx.x;
    const int warp  = tid >> 5;          // 0..7
    const int lane  = tid & 31;

    // Select source tensor for this sample (only this one is read)
    const int q  = qual[b];
    const float* __restrict__ src = (q == 1) ? feat : feat_p;
    const int lb = label[b] & 1;   // mask: guaranteed in-bounds gather
    const float* __restrict__ af_pos = avg_feat + (size_t)lb * C_;
    const float* __restrict__ af_neg = avg_feat + (size_t)(1 - lb) * C_;

    float acc = 0.0f;

    // Each warp handles 8 channels; process 2 per iteration so 4 independent
    // LDG.128 are in flight per thread before any shuffle dependency.
    #pragma unroll
    for (int it = 0; it < 4; ++it) {
        const int c0 = chunk * CPB + warp + it * 16;
        const int c1 = c0 + 8;
        const float4* __restrict__ rowA =
            reinterpret_cast<const float4*>(src + ((size_t)b * C_ + c0) * HW_);
        const float4* __restrict__ rowB =
            reinterpret_cast<const float4*>(src + ((size_t)b * C_ + c1) * HW_);

        // 49 float4 per row: lane loads [lane] and (lane<17) [lane+32]
        float4 a0 = rowA[lane];
        float4 b0 = rowB[lane];
        float4 a1, b1;
        const bool tail = (lane < VEC_ - 32);
        if (tail) { a1 = rowA[lane + 32]; b1 = rowB[lane + 32]; }

        float sA = a0.x + a0.y + a0.z + a0.w;
        float sB = b0.x + b0.y + b0.z + b0.w;
        if (tail) {
            sA += a1.x + a1.y + a1.z + a1.w;
            sB += b1.x + b1.y + b1.z + b1.w;
        }
        #pragma unroll
        for (int off = 16; off > 0; off >>= 1) {
            sA += __shfl_xor_sync(0xFFFFFFFFu, sA, off);
            sB += __shfl_xor_sync(0xFFFFFFFFu, sB, off);
        }

        if (lane == 0) {
            const float selA = sA * (1.0f / (float)HW_);
            const float selB = sB * (1.0f / (float)HW_);
            acc += fmaxf(fabsf(selA - af_pos[c0] + EPS) - fabsf(selA - af_neg[c0] + EPS) + MARGIN, 0.0f);
            acc += fmaxf(fabsf(selB - af_pos[c1] + EPS) - fabsf(selB - af_neg[c1] + EPS) + MARGIN, 0.0f);
        }
    }

    // Block reduce the 8 warp-leader partials (fixed order -> deterministic)
    __shared__ float warp_acc[8];
    __shared__ bool  is_last;
    if (lane == 0) warp_acc[warp] = acc;
    __syncthreads();
    if (tid == 0) {
        float t = 0.0f;
        #pragma unroll
        for (int w = 0; w < 8; ++w) t += warp_acc[w];
        // L2-resident store so the fenced value is globally visible
        __stcg(&g_partials[b * CHUNKS + chunk], t * (1.0f / (float)C_));
        __threadfence();
        unsigned int ticket = atomicAdd(&g_ticket, 1u);
        is_last = (ticket == NPART - 1);
    }
    __syncthreads();

    // Last block to finish performs the deterministic final sum.
    if (is_last) {
        if (tid == 0) g_ticket = 0;   // reset for next graph replay
        float s = 0.0f;
        #pragma unroll
        for (int i = 0; i < NPART / THREADS; ++i)       // 8 each, fixed order
            s += __ldcg(&g_partials[tid + i * THREADS]);

        __shared__ float sm[THREADS];
        sm[tid] = s;
        __syncthreads();
        #pragma unroll
        for (int step = THREADS / 2; step > 0; step >>= 1) {
            if (tid < step) sm[tid] += sm[tid + step];
            __syncthreads();
        }
        if (tid == 0) out[0] = sm[0];
    }
}

extern "C" void kernel_launch(void* const* d_in, const int* in_sizes, int n_in,
                              void* d_out, int out_size)
{
    const float* feat     = (const float*)d_in[0];
    const float* feat_p   = (const float*)d_in[1];
    const float* avg_feat = (const float*)d_in[2];
    const int*   qual     = (const int*)d_in[3];
    const int*   label    = (const int*)d_in[4];
    float* out = (float*)d_out;

    dim3 grid(CHUNKS, B_);
    ffl_fused_kernel<<<grid, THREADS>>>(feat, feat_p, avg_feat, qual, label, out);
}